// round 10
// baseline (speedup 1.0000x reference)
#include <cuda_runtime.h>
#include <cuda_bf16.h>
#include <cstdint>
#include <math.h>

#define LSEQ 256
#define BSZ  64
#define NH   8
#define DH   128
#define DM   1024
#define NQ   4096
#define MROWS (LSEQ*BSZ)
#define SCALE_F 0.08838834764831845f
#define LN_EPS_F 1e-5f

// ---- scratch (static device arrays; no allocation) ----
__device__ __align__(256) float g_x  [(size_t)MROWS * DM];           // h + attn_out fp32
__device__ __align__(256) __nv_bfloat16 g_qkvb[(size_t)MROWS * NQ];  // phi(q,k1,k2), v  bf16
__device__ __align__(256) __nv_bfloat16 g_lob[(size_t)MROWS * DM];   // layer_out bf16
__device__ __align__(256) int8_t g_h8 [(size_t)MROWS * DM];          // h quantized s8
__device__ __align__(256) int8_t g_wq8[(size_t)NQ * DM];             // Wqkv s8
__device__ __align__(256) int8_t g_wo8[(size_t)DM * DM];             // Wo s8
__device__ __align__(256) int8_t g_lo8[(size_t)MROWS * DM];          // layer_out s8
__device__ __align__(256) float g_sH [MROWS];                        // row scales
__device__ __align__(256) float g_sWq[NQ];
__device__ __align__(256) float g_sWo[DM];
__device__ __align__(256) float g_sLo[MROWS];

// ======================= helpers =======================
__device__ __forceinline__ uint32_t smem_u32(const void* p) {
    uint32_t a;
    asm("{ .reg .u64 t; cvta.to.shared.u64 t, %1; cvt.u32.u64 %0, t; }" : "=r"(a) : "l"(p));
    return a;
}
__device__ __forceinline__ void cp16(void* s, const void* g) {
    uint32_t sa = smem_u32(s);
    asm volatile("cp.async.cg.shared.global [%0], [%1], 16;" :: "r"(sa), "l"(g));
}
#define LDSM4(r0, r1, r2, r3, addr) \
    asm volatile("ldmatrix.sync.aligned.m8n8.x4.shared.b16 {%0,%1,%2,%3}, [%4];" \
                 : "=r"(r0), "=r"(r1), "=r"(r2), "=r"(r3) : "r"(addr))
#define LDSM4T(r0, r1, r2, r3, addr) \
    asm volatile("ldmatrix.sync.aligned.m8n8.x4.trans.shared.b16 {%0,%1,%2,%3}, [%4];" \
                 : "=r"(r0), "=r"(r1), "=r"(r2), "=r"(r3) : "r"(addr))
// s8 x s8 -> s32 IMMA (2x rate class)
__device__ __forceinline__ void mma_s8(int* d, const uint32_t* a,
                                       uint32_t b0, uint32_t b1) {
    asm volatile(
        "mma.sync.aligned.m16n8k32.row.col.s32.s8.s8.s32 "
        "{%0,%1,%2,%3}, {%4,%5,%6,%7}, {%8,%9}, {%0,%1,%2,%3};"
        : "+r"(d[0]), "+r"(d[1]), "+r"(d[2]), "+r"(d[3])
        : "r"(a[0]), "r"(a[1]), "r"(a[2]), "r"(a[3]), "r"(b0), "r"(b1));
}
// bf16 operands, fp32 accumulators (attention — validated R7 path)
__device__ __forceinline__ void mma_bf16(float* d, const uint32_t* a,
                                         uint32_t b0, uint32_t b1) {
    asm volatile(
        "mma.sync.aligned.m16n8k16.row.col.f32.bf16.bf16.f32 "
        "{%0,%1,%2,%3}, {%4,%5,%6,%7}, {%8,%9}, {%0,%1,%2,%3};"
        : "+f"(d[0]), "+f"(d[1]), "+f"(d[2]), "+f"(d[3])
        : "r"(a[0]), "r"(a[1]), "r"(a[2]), "r"(a[3]), "r"(b0), "r"(b1));
}
__device__ __forceinline__ uint32_t pack_bf16x2(float x, float y) {
    __nv_bfloat162 p = __floats2bfloat162_rn(x, y);
    return *(uint32_t*)&p;
}

// ======================= per-row abs-max quantization to s8 =======================
// one block (256 thr) per row of 1024; SRC 0 = fp32, 1 = bf16
template<int SRC>
__global__ void __launch_bounds__(256)
quant_rows(const void* __restrict__ src, int8_t* __restrict__ dst,
           float* __restrict__ scale)
{
    __shared__ float red[8];
    const int row = blockIdx.x, tid = threadIdx.x;
    const int lane = tid & 31, wid = tid >> 5;
    float v[4];
    if (SRC == 0) {
        float4 x = ((const float4*)((const float*)src + (size_t)row * DM))[tid];
        v[0] = x.x; v[1] = x.y; v[2] = x.z; v[3] = x.w;
    } else {
        uint2 u = ((const uint2*)((const __nv_bfloat16*)src + (size_t)row * DM))[tid];
        float2 a = __bfloat1622float2(*(__nv_bfloat162*)&u.x);
        float2 b = __bfloat1622float2(*(__nv_bfloat162*)&u.y);
        v[0] = a.x; v[1] = a.y; v[2] = b.x; v[3] = b.y;
    }
    float m = fmaxf(fmaxf(fabsf(v[0]), fabsf(v[1])), fmaxf(fabsf(v[2]), fabsf(v[3])));
#pragma unroll
    for (int o = 16; o > 0; o >>= 1) m = fmaxf(m, __shfl_xor_sync(0xffffffffu, m, o));
    if (lane == 0) red[wid] = m;
    __syncthreads();
    float mm = red[0];
#pragma unroll
    for (int i = 1; i < 8; i++) mm = fmaxf(mm, red[i]);
    mm = fmaxf(mm, 1e-20f);
    const float inv = 127.f / mm;
    char4 o;
    o.x = (char)__float2int_rn(v[0] * inv);
    o.y = (char)__float2int_rn(v[1] * inv);
    o.z = (char)__float2int_rn(v[2] * inv);
    o.w = (char)__float2int_rn(v[3] * inv);
    ((char4*)(dst + (size_t)row * DM))[tid] = o;
    if (tid == 0) scale[row] = mm * (1.f / 127.f);
}

// ======================= s8 IMMA GEMM: C = (A*sA) * (B*sB)^T =======================
// CTA 128x128, 8 warps (2x4), warp 64x32, stage = 64 bytes of K, 3-stage cp.async,
// ldmatrix.x4 over b16 units (s8 m16n8k32 frags == f16 m16n8k16 frags, 2 bytes/slot).
// MODE 0: C = g_qkvb (bf16, NC=4096), epilogue = dequant + phi on q/k1/k2 groups
// MODE 1: C = g_x (fp32, NC=1024), epilogue = dequant + residual R (h fp32)
#define KBY 64                       // K bytes per stage
#define GITERS (DM / KBY)            // 16
#define STG 3
#define RSB 80                       // row stride bytes (padded)
#define STAGE_BYTES (128 * RSB)      // 10240
#define GEMM_SMEM_BYTES (STG * 2 * STAGE_BYTES)   // 61440

template<int MODE>
__global__ void __launch_bounds__(256, 2)
gemm_s8(const int8_t* __restrict__ A, const float* __restrict__ sA,
        const int8_t* __restrict__ Bm, const float* __restrict__ sB,
        const float* __restrict__ R, void* __restrict__ Cv, int NC)
{
    extern __shared__ __align__(16) char smraw[];
    float* smf = (float*)smraw;
    const int tid = threadIdx.x;
    const int wid = tid >> 5, lane = tid & 31;
    const int wR = wid >> 2, wC = wid & 3;
    const int qr = lane >> 2, qc = lane & 3;
    const int m0 = blockIdx.y * 128, n0 = blockIdx.x * 128;

    int acc[4][4][4];
#pragma unroll
    for (int mt = 0; mt < 4; mt++)
#pragma unroll
        for (int nt = 0; nt < 4; nt++)
#pragma unroll
            for (int c = 0; c < 4; c++) acc[mt][nt][c] = 0;

    const int lrow = tid >> 2, lcB = (tid & 3) * 16;   // 4 x 16B chunks per 64B row

    auto issue = [&](int it) {
        if (it < GITERS) {
            const int s = it % STG;
            char* As = smraw + s * 2 * STAGE_BYTES;
            char* Bs = As + STAGE_BYTES;
            const int k0 = it * KBY;
            cp16(&As[lrow * RSB + lcB],        A  + (size_t)(m0 + lrow) * DM + k0 + lcB);
            cp16(&As[(lrow + 64) * RSB + lcB], A  + (size_t)(m0 + lrow + 64) * DM + k0 + lcB);
            cp16(&Bs[lrow * RSB + lcB],        Bm + (size_t)(n0 + lrow) * DM + k0 + lcB);
            cp16(&Bs[(lrow + 64) * RSB + lcB], Bm + (size_t)(n0 + lrow + 64) * DM + k0 + lcB);
        }
        asm volatile("cp.async.commit_group;" ::: "memory");
    };

    issue(0);
    issue(1);

    // ldmatrix lane byte offsets (identical to validated R7 formulas, bytes)
    const uint32_t a_lane_off = (wR * 64 + (lane & 15)) * RSB + ((lane >> 4) << 4);
    const uint32_t b_lane_off = (wC * 32 + ((lane >> 4) << 3) + (lane & 7)) * RSB +
                                (((lane >> 3) & 1) << 4);

#pragma unroll 1
    for (int it = 0; it < GITERS; ++it) {
        asm volatile("cp.async.wait_group 1;" ::: "memory");
        __syncthreads();
        issue(it + 2);

        const int s = it % STG;
        const uint32_t abase = smem_u32(smraw + s * 2 * STAGE_BYTES) + a_lane_off;
        const uint32_t bbase = smem_u32(smraw + s * 2 * STAGE_BYTES + STAGE_BYTES) + b_lane_off;

#pragma unroll
        for (int ks = 0; ks < 2; ks++) {          // 2 x k32 (32 bytes each)
            uint32_t a[4][4], b[2][4];
#pragma unroll
            for (int mt = 0; mt < 4; mt++)
                LDSM4(a[mt][0], a[mt][1], a[mt][2], a[mt][3],
                      abase + mt * (16 * RSB) + ks * 32);
#pragma unroll
            for (int nt2 = 0; nt2 < 2; nt2++)
                LDSM4(b[nt2][0], b[nt2][1], b[nt2][2], b[nt2][3],
                      bbase + nt2 * (16 * RSB) + ks * 32);
#pragma unroll
            for (int mt = 0; mt < 4; mt++) {
                mma_s8(acc[mt][0], a[mt], b[0][0], b[0][1]);
                mma_s8(acc[mt][1], a[mt], b[0][2], b[0][3]);
                mma_s8(acc[mt][2], a[mt], b[1][0], b[1][1]);
                mma_s8(acc[mt][3], a[mt], b[1][2], b[1][3]);
            }
        }
    }
    asm volatile("cp.async.wait_group 0;" ::: "memory");
    __syncthreads();

    // dequantize: facc = s32 * sA[row] * sB[col]
    float facc[4][4][4];
#pragma unroll
    for (int mt = 0; mt < 4; mt++) {
#pragma unroll
        for (int hh = 0; hh < 2; hh++) {
            const int row = m0 + wR * 64 + mt * 16 + hh * 8 + qr;
            const float sa = sA[row];
#pragma unroll
            for (int nt = 0; nt < 4; nt++) {
                const int col = n0 + wC * 32 + nt * 8 + qc * 2;
                const float2 sb = *(const float2*)(sB + col);
                facc[mt][nt][hh * 2]     = (float)acc[mt][nt][hh * 2]     * sa * sb.x;
                facc[mt][nt][hh * 2 + 1] = (float)acc[mt][nt][hh * 2 + 1] * sa * sb.y;
            }
        }
    }

    if (MODE == 0) {
        __nv_bfloat16* C = (__nv_bfloat16*)Cv;
        const int which = (n0 >> 7) & 3;   // 0=q,1=k1,2=k2,3=v
        float inv[4][2];
#pragma unroll
        for (int mt = 0; mt < 4; mt++) { inv[mt][0] = 1.f; inv[mt][1] = 1.f; }
        if (which < 3) {
#pragma unroll
            for (int mt = 0; mt < 4; mt++)
#pragma unroll
                for (int nt = 0; nt < 4; nt++)
#pragma unroll
                    for (int c = 0; c < 4; c++) {
                        float x = facc[mt][nt][c];
                        facc[mt][nt][c] = (x > 0.f) ? x + 1.f : __expf(x);
                    }
#pragma unroll
            for (int mt = 0; mt < 4; mt++)
#pragma unroll
                for (int hh = 0; hh < 2; hh++) {
                    float v = 0.f;
#pragma unroll
                    for (int nt = 0; nt < 4; nt++)
                        v += facc[mt][nt][hh * 2] + facc[mt][nt][hh * 2 + 1];
                    v += __shfl_xor_sync(0xffffffffu, v, 1);
                    v += __shfl_xor_sync(0xffffffffu, v, 2);
                    if (qc == 0)
                        smf[(wR * 64 + mt * 16 + hh * 8 + qr) * 4 + wC] = v;
                }
            __syncthreads();
#pragma unroll
            for (int mt = 0; mt < 4; mt++)
#pragma unroll
                for (int hh = 0; hh < 2; hh++) {
                    int row = wR * 64 + mt * 16 + hh * 8 + qr;
                    float s = smf[row * 4 + 0] + smf[row * 4 + 1] +
                              smf[row * 4 + 2] + smf[row * 4 + 3];
                    inv[mt][hh] = 1.f / s;
                }
        }
#pragma unroll
        for (int mt = 0; mt < 4; mt++)
#pragma unroll
            for (int hh = 0; hh < 2; hh++) {
                const int row = m0 + wR * 64 + mt * 16 + hh * 8 + qr;
                const float iv = inv[mt][hh];
#pragma unroll
                for (int nt = 0; nt < 4; nt++) {
                    uint32_t o = pack_bf16x2(facc[mt][nt][hh * 2] * iv,
                                             facc[mt][nt][hh * 2 + 1] * iv);
                    *(uint32_t*)(C + (size_t)row * NC + n0 + wC * 32 + nt * 8 + qc * 2) = o;
                }
            }
    } else {
        float* C = (float*)Cv;
#pragma unroll
        for (int mt = 0; mt < 4; mt++)
#pragma unroll
            for (int hh = 0; hh < 2; hh++) {
                const int row = m0 + wR * 64 + mt * 16 + hh * 8 + qr;
#pragma unroll
                for (int nt = 0; nt < 4; nt++) {
                    const int col = n0 + wC * 32 + nt * 8 + qc * 2;
                    float2 rr = *(const float2*)(R + (size_t)row * DM + col);
                    float2 o;
                    o.x = facc[mt][nt][hh * 2]     + rr.x;
                    o.y = facc[mt][nt][hh * 2 + 1] + rr.y;
                    *(float2*)(C + (size_t)row * NC + col) = o;
                }
            }
    }
}

// ======================= tensor-core dual causal linear attention (R7, validated) =======================
#define ARS 136                      // qkv tile row stride (halves)
#define PRS 72                       // P tile row stride (halves)
#define ATTN_SMEM_HALVES (4 * 64 * ARS + 64 * PRS)
#define ATTN_SMEM_BYTES (ATTN_SMEM_HALVES * 2)   // 78848

__global__ void __launch_bounds__(256, 2)
attn_mma(const float* __restrict__ pi0)
{
    extern __shared__ __align__(16) __nv_bfloat16 smh[];
    __nv_bfloat16* Qs  = smh;
    __nv_bfloat16* K1s = Qs  + 64 * ARS;
    __nv_bfloat16* K2s = K1s + 64 * ARS;
    __nv_bfloat16* Vs  = K2s + 64 * ARS;
    __nv_bfloat16* Ps  = Vs  + 64 * ARS;
    uint32_t* Pu = (uint32_t*)Ps;

    const int tid = threadIdx.x;
    const int wid = tid >> 5, lane = tid & 31;
    const int wm = wid >> 1, wn = wid & 1;
    const int qr = lane >> 2, qc = lane & 3;
    const int tt = blockIdx.x;
    const int bh = blockIdx.y;
    const int b  = bh >> 3, head = bh & 7;
    const int t0 = tt * 64;

    const int lrow = tid >> 2, lch = (tid & 3) * 4;

    // load Q tile (full 64 x 128 halves)
#pragma unroll
    for (int c = 0; c < 4; c++) {
        int ch = lch + c;
        cp16(&Qs[lrow * ARS + ch * 8],
             g_qkvb + ((size_t)(t0 + lrow) * BSZ + b) * NQ + head * 512 + ch * 8);
    }
    asm volatile("cp.async.commit_group;" ::: "memory");

    const float pa = fminf(fmaxf(pi0[head * 256 + t0 + wm * 16 + qr], 0.f), 1.f);
    const float pb = fminf(fmaxf(pi0[head * 256 + t0 + wm * 16 + qr + 8], 0.f), 1.f);

    float o[8][4];
#pragma unroll
    for (int i = 0; i < 8; i++)
#pragma unroll
        for (int c = 0; c < 4; c++) o[i][c] = 0.f;

    const uint32_t qa_off = ((wm * 16 + (lane & 15)) * ARS + ((lane >> 4) << 3)) * 2;
    const uint32_t kb_off = ((wn * 32 + ((lane >> 4) << 3) + (lane & 7)) * ARS +
                             (((lane >> 3) & 1) << 3)) * 2;
    const uint32_t pa_off = ((wm * 16 + (lane & 15)) * PRS + ((lane >> 4) << 3)) * 2;
    const uint32_t vt_off = ((lane & 15) * ARS + wn * 64 + ((lane >> 4) << 3)) * 2;
    const uint32_t qbase = smem_u32(Qs), k1base = smem_u32(K1s), k2base = smem_u32(K2s);
    const uint32_t pbase = smem_u32(Ps), vbase = smem_u32(Vs);

#pragma unroll 1
    for (int st = 0; st <= tt; st++) {
        const int s0 = st * 64;
        if (st > 0) __syncthreads();
        {
            size_t gb = ((size_t)(s0 + lrow) * BSZ + b) * NQ + head * 512;
#pragma unroll
            for (int c = 0; c < 4; c++) {
                int ch = lch + c;
                cp16(&K1s[lrow * ARS + ch * 8], g_qkvb + gb + 128 + ch * 8);
                cp16(&K2s[lrow * ARS + ch * 8], g_qkvb + gb + 256 + ch * 8);
                cp16(&Vs [lrow * ARS + ch * 8], g_qkvb + gb + 384 + ch * 8);
            }
        }
        asm volatile("cp.async.commit_group;" ::: "memory");
        asm volatile("cp.async.wait_group 0;" ::: "memory");
        __syncthreads();

        // ---- S phase ----
        float s1[4][4], s2[4][4];
#pragma unroll
        for (int nc = 0; nc < 4; nc++)
#pragma unroll
            for (int c = 0; c < 4; c++) { s1[nc][c] = 0.f; s2[nc][c] = 0.f; }

#pragma unroll
        for (int ks = 0; ks < 8; ks++) {
            uint32_t a[4], b1[2][4], b2[2][4];
            LDSM4(a[0], a[1], a[2], a[3], qbase + qa_off + ks * 32);
#pragma unroll
            for (int g = 0; g < 2; g++) {
                LDSM4(b1[g][0], b1[g][1], b1[g][2], b1[g][3],
                      k1base + kb_off + g * (16 * ARS * 2) + ks * 32);
                LDSM4(b2[g][0], b2[g][1], b2[g][2], b2[g][3],
                      k2base + kb_off + g * (16 * ARS * 2) + ks * 32);
            }
            mma_bf16(s1[0], a, b1[0][0], b1[0][1]);
            mma_bf16(s1[1], a, b1[0][2], b1[0][3]);
            mma_bf16(s1[2], a, b1[1][0], b1[1][1]);
            mma_bf16(s1[3], a, b1[1][2], b1[1][3]);
            mma_bf16(s2[0], a, b2[0][0], b2[0][1]);
            mma_bf16(s2[1], a, b2[0][2], b2[0][3]);
            mma_bf16(s2[2], a, b2[1][0], b2[1][1]);
            mma_bf16(s2[3], a, b2[1][2], b2[1][3]);
        }

        // ---- combine + mask -> P (bf16) ----
        const bool diag = (st == tt);
        const int tg0 = wm * 16 + qr, tg1 = tg0 + 8;
#pragma unroll
        for (int nc = 0; nc < 4; nc++) {
            const int c0 = wn * 32 + nc * 8 + qc * 2, c1 = c0 + 1;
            float v00 = s2[nc][0] + pa * (s1[nc][0] - s2[nc][0]);
            float v01 = s2[nc][1] + pa * (s1[nc][1] - s2[nc][1]);
            float v10 = s2[nc][2] + pb * (s1[nc][2] - s2[nc][2]);
            float v11 = s2[nc][3] + pb * (s1[nc][3] - s2[nc][3]);
            if (diag) {
                if (c0 > tg0) v00 = 0.f;
                if (c1 > tg0) v01 = 0.f;
                if (c0 > tg1) v10 = 0.f;
                if (c1 > tg1) v11 = 0.f;
            }
            Pu[tg0 * (PRS / 2) + (c0 >> 1)] = pack_bf16x2(v00, v01);
            Pu[tg1 * (PRS / 2) + (c0 >> 1)] = pack_bf16x2(v10, v11);
        }
        __syncthreads();

        // ---- PV phase ----
#pragma unroll
        for (int ks = 0; ks < 4; ks++) {
            uint32_t a[4];
            LDSM4(a[0], a[1], a[2], a[3], pbase + pa_off + ks * 32);
#pragma unroll
            for (int nc2 = 0; nc2 < 4; nc2++) {
                uint32_t b[4];
                LDSM4T(b[0], b[1], b[2], b[3],
                       vbase + vt_off + ks * (16 * ARS * 2) + nc2 * 32);
                mma_bf16(o[nc2 * 2],     a, b[0], b[1]);
                mma_bf16(o[nc2 * 2 + 1], a, b[2], b[3]);
            }
        }
    }

    // ---- store O * SCALE -> g_lob bf16 ----
#pragma unroll
    for (int i = 0; i < 8; i++) {
        const int dh = head * DH + wn * 64 + i * 8 + qc * 2;
        const int ta = t0 + wm * 16 + qr, tb2 = ta + 8;
        *(uint32_t*)(g_lob + ((size_t)ta * BSZ + b) * DM + dh) =
            pack_bf16x2(SCALE_F * o[i][0], SCALE_F * o[i][1]);
        *(uint32_t*)(g_lob + ((size_t)tb2 * BSZ + b) * DM + dh) =
            pack_bf16x2(SCALE_F * o[i][2], SCALE_F * o[i][3]);
    }
}

// ======================= LayerNorm =======================
__global__ void __launch_bounds__(256)
ln_kernel(const float* __restrict__ gamma, const float* __restrict__ beta,
          float* __restrict__ out)
{
    __shared__ float red[8];
    const int r = blockIdx.x, tid = threadIdx.x;
    const int lane = tid & 31, wid = tid >> 5;
    float4 v = *(const float4*)&g_x[(size_t)r * DM + tid * 4];
    float s = v.x + v.y + v.z + v.w;
#pragma unroll
    for (int o = 16; o > 0; o >>= 1) s += __shfl_xor_sync(0xffffffffu, s, o);
    if (lane == 0) red[wid] = s;
    __syncthreads();
    float tot = 0.f;
#pragma unroll
    for (int i = 0; i < 8; i++) tot += red[i];
    float mu = tot * (1.f / DM);
    float d0 = v.x - mu, d1 = v.y - mu, d2 = v.z - mu, d3 = v.w - mu;
    float sq = d0*d0 + d1*d1 + d2*d2 + d3*d3;
#pragma unroll
    for (int o = 16; o > 0; o >>= 1) sq += __shfl_xor_sync(0xffffffffu, sq, o);
    __syncthreads();
    if (lane == 0) red[wid] = sq;
    __syncthreads();
    float tot2 = 0.f;
#pragma unroll
    for (int i = 0; i < 8; i++) tot2 += red[i];
    float inv = rsqrtf(tot2 * (1.f / DM) + LN_EPS_F);
    float4 g = *(const float4*)&gamma[tid * 4];
    float4 bt = *(const float4*)&beta[tid * 4];
    float4 o;
    o.x = g.x * d0 * inv + bt.x;
    o.y = g.y * d1 * inv + bt.y;
    o.z = g.z * d2 * inv + bt.z;
    o.w = g.w * d3 * inv + bt.w;
    *(float4*)&out[(size_t)r * DM + tid * 4] = o;
}

// ======================= launch =======================
extern "C" void kernel_launch(void* const* d_in, const int* in_sizes, int n_in,
                              void* d_out, int out_size)
{
    const float* h     = (const float*)d_in[0];
    const float* Wqkv  = (const float*)d_in[1];
    const float* Wo    = (const float*)d_in[2];
    const float* pi0   = (const float*)d_in[3];
    const float* gamma = (const float*)d_in[4];
    const float* beta  = (const float*)d_in[5];
    float* out = (float*)d_out;

    float *p_x, *p_sH, *p_sWq, *p_sWo, *p_sLo;
    int8_t *p_h8, *p_wq8, *p_wo8, *p_lo8;
    __nv_bfloat16 *p_qkvb, *p_lob;
    cudaGetSymbolAddress((void**)&p_x, g_x);
    cudaGetSymbolAddress((void**)&p_sH, g_sH);
    cudaGetSymbolAddress((void**)&p_sWq, g_sWq);
    cudaGetSymbolAddress((void**)&p_sWo, g_sWo);
    cudaGetSymbolAddress((void**)&p_sLo, g_sLo);
    cudaGetSymbolAddress((void**)&p_h8, g_h8);
    cudaGetSymbolAddress((void**)&p_wq8, g_wq8);
    cudaGetSymbolAddress((void**)&p_wo8, g_wo8);
    cudaGetSymbolAddress((void**)&p_lo8, g_lo8);
    cudaGetSymbolAddress((void**)&p_qkvb, g_qkvb);
    cudaGetSymbolAddress((void**)&p_lob, g_lob);

    cudaFuncSetAttribute(gemm_s8<0>, cudaFuncAttributeMaxDynamicSharedMemorySize, GEMM_SMEM_BYTES);
    cudaFuncSetAttribute(gemm_s8<1>, cudaFuncAttributeMaxDynamicSharedMemorySize, GEMM_SMEM_BYTES);
    cudaFuncSetAttribute(attn_mma, cudaFuncAttributeMaxDynamicSharedMemorySize, ATTN_SMEM_BYTES);

    // 0. quantize h, Wqkv, Wo (per-row abs-max -> s8 + scale)
    quant_rows<0><<<MROWS, 256>>>(h, p_h8, p_sH);
    quant_rows<0><<<NQ, 256>>>(Wqkv, p_wq8, p_sWq);
    quant_rows<0><<<DM, 256>>>(Wo, p_wo8, p_sWo);

    // 1. qkv = h @ Wqkv^T (s8 IMMA), dequant + phi fused, bf16 out
    gemm_s8<0><<<dim3(NQ / 128, MROWS / 128), 256, GEMM_SMEM_BYTES>>>(
        p_h8, p_sH, p_wq8, p_sWq, nullptr, p_qkvb, NQ);

    // 2. tensor-core dual causal linear attention -> g_lob (bf16)
    attn_mma<<<dim3(LSEQ / 64, BSZ * NH), 256, ATTN_SMEM_BYTES>>>(pi0);

    // 3. quantize layer_out, then x = layer_out @ Wo^T + h (s8 IMMA, residual fused)
    quant_rows<1><<<MROWS, 256>>>(p_lob, p_lo8, p_sLo);
    gemm_s8<1><<<dim3(DM / 128, MROWS / 128), 256, GEMM_SMEM_BYTES>>>(
        p_lo8, p_sLo, p_wo8, p_sWo, h, p_x, DM);

    // 4. LayerNorm -> out
    ln_kernel<<<MROWS, 256>>>(gamma, beta, out);
}

// round 13
// speedup vs baseline: 1.5402x; 1.5402x over previous
#include <cuda_runtime.h>
#include <cuda_bf16.h>
#include <cstdint>
#include <math.h>

#define LSEQ 256
#define BSZ  64
#define NH   8
#define DH   128
#define DM   1024
#define NQ   4096
#define MROWS (LSEQ*BSZ)
#define SCALE_F 0.08838834764831845f
#define LN_EPS_F 1e-5f

// ---- scratch (static device arrays; no allocation) ----
__device__ __align__(256) float g_x  [(size_t)MROWS * DM];           // h + attn_out fp32
__device__ __align__(256) __nv_bfloat16 g_qkvb[(size_t)MROWS * NQ];  // phi(q,k1,k2), v  bf16
__device__ __align__(256) __nv_bfloat16 g_hb [(size_t)MROWS * DM];   // h bf16
__device__ __align__(256) __nv_bfloat16 g_wqb[(size_t)NQ * DM];      // Wqkv bf16
__device__ __align__(256) __nv_bfloat16 g_wob[(size_t)DM * DM];      // Wo bf16
__device__ __align__(256) __nv_bfloat16 g_lob[(size_t)MROWS * DM];   // layer_out bf16

// ======================= helpers =======================
__device__ __forceinline__ uint32_t smem_u32(const void* p) {
    uint32_t a;
    asm("{ .reg .u64 t; cvta.to.shared.u64 t, %1; cvt.u32.u64 %0, t; }" : "=r"(a) : "l"(p));
    return a;
}
__device__ __forceinline__ void cp16(void* s, const void* g) {
    uint32_t sa = smem_u32(s);
    asm volatile("cp.async.cg.shared.global [%0], [%1], 16;" :: "r"(sa), "l"(g));
}
#define LDSM4(r0, r1, r2, r3, addr) \
    asm volatile("ldmatrix.sync.aligned.m8n8.x4.shared.b16 {%0,%1,%2,%3}, [%4];" \
                 : "=r"(r0), "=r"(r1), "=r"(r2), "=r"(r3) : "r"(addr))
#define LDSM4T(r0, r1, r2, r3, addr) \
    asm volatile("ldmatrix.sync.aligned.m8n8.x4.trans.shared.b16 {%0,%1,%2,%3}, [%4];" \
                 : "=r"(r0), "=r"(r1), "=r"(r2), "=r"(r3) : "r"(addr))
__device__ __forceinline__ void mma_bf16(float* d, const uint32_t* a,
                                         uint32_t b0, uint32_t b1) {
    asm volatile(
        "mma.sync.aligned.m16n8k16.row.col.f32.bf16.bf16.f32 "
        "{%0,%1,%2,%3}, {%4,%5,%6,%7}, {%8,%9}, {%0,%1,%2,%3};"
        : "+f"(d[0]), "+f"(d[1]), "+f"(d[2]), "+f"(d[3])
        : "r"(a[0]), "r"(a[1]), "r"(a[2]), "r"(a[3]), "r"(b0), "r"(b1));
}
__device__ __forceinline__ uint32_t pack_bf16x2(float x, float y) {
    __nv_bfloat162 p = __floats2bfloat162_rn(x, y);
    return *(uint32_t*)&p;
}

// ======================= fp32 -> bf16 conversion pass =======================
__global__ void __launch_bounds__(256)
cvt_bf16(const float* __restrict__ src, __nv_bfloat16* __restrict__ dst)
{
    size_t i = ((size_t)blockIdx.x * 256 + threadIdx.x) * 4;
    float4 v = *(const float4*)(src + i);
    uint2 o;
    o.x = pack_bf16x2(v.x, v.y);
    o.y = pack_bf16x2(v.z, v.w);
    *(uint2*)(dst + i) = o;
}

// ======================= bf16 mma.sync GEMM: C = A * B^T =======================
// CTA 128x128, 8 warps (2x4), warp 64x32, KB=64 halves/stage, 3-stage cp.async,
// ldmatrix.x4, 72-half padded row stride (conflict-free LDSM).
// MODE 0: C = g_qkvb (bf16, NC=4096), epilogue = phi on q/k1/k2 groups
// MODE 1: C = g_x (fp32, NC=1024), epilogue = + residual R (h fp32)
#define KB 64
#define GITERS (DM / KB)            // 16
#define STG 3
#define RSH 72                      // row stride in halves (144 bytes)
#define STAGE_HALVES (128 * RSH)    // 9216 halves = 18432 B
#define GEMM_SMEM_BYTES (STG * 2 * STAGE_HALVES * 2)   // 110592

template<int MODE>
__global__ void __launch_bounds__(256, 2)
gemm_mma(const __nv_bfloat16* __restrict__ A, const __nv_bfloat16* __restrict__ Bm,
         const float* __restrict__ R, void* __restrict__ Cv, int NC)
{
    extern __shared__ __align__(16) char smraw[];
    __nv_bfloat16* smh = (__nv_bfloat16*)smraw;
    float* smf = (float*)smraw;
    const int tid = threadIdx.x;
    const int wid = tid >> 5, lane = tid & 31;
    const int wR = wid >> 2, wC = wid & 3;
    const int qr = lane >> 2, qc = lane & 3;
    const int m0 = blockIdx.y * 128, n0 = blockIdx.x * 128;

    float acc[4][4][4];
#pragma unroll
    for (int mt = 0; mt < 4; mt++)
#pragma unroll
        for (int nt = 0; nt < 4; nt++)
#pragma unroll
            for (int c = 0; c < 4; c++) acc[mt][nt][c] = 0.f;

    const int lrow = tid >> 1, lcb = (tid & 1) * 32;   // 2 threads/row, 4 chunks each

    auto issue = [&](int it) {
        if (it < GITERS) {
            const int s = it % STG;
            __nv_bfloat16* As = smh + s * 2 * STAGE_HALVES;
            __nv_bfloat16* Bs = As + STAGE_HALVES;
            const int k0 = it * KB;
#pragma unroll
            for (int c = 0; c < 4; c++) {
                const int hc = lcb + c * 8;
                cp16(&As[lrow * RSH + hc], A  + (size_t)(m0 + lrow) * DM + k0 + hc);
                cp16(&Bs[lrow * RSH + hc], Bm + (size_t)(n0 + lrow) * DM + k0 + hc);
            }
        }
        asm volatile("cp.async.commit_group;" ::: "memory");
    };

    issue(0);
    issue(1);

    const uint32_t a_lane_off = ((wR * 64 + (lane & 15)) * RSH + ((lane >> 4) << 3)) * 2;
    const uint32_t b_lane_off = ((wC * 32 + ((lane >> 4) << 3) + (lane & 7)) * RSH +
                                 (((lane >> 3) & 1) << 3)) * 2;

#pragma unroll 1
    for (int it = 0; it < GITERS; ++it) {
        asm volatile("cp.async.wait_group 1;" ::: "memory");
        __syncthreads();
        issue(it + 2);

        const int s = it % STG;
        const uint32_t abase = smem_u32(smh + s * 2 * STAGE_HALVES) + a_lane_off;
        const uint32_t bbase = smem_u32(smh + s * 2 * STAGE_HALVES + STAGE_HALVES) + b_lane_off;

#pragma unroll
        for (int ks = 0; ks < 4; ks++) {    // 4 x k16 (32 bytes each within 64-half stage)
            uint32_t a[4][4], b[2][4];
#pragma unroll
            for (int mt = 0; mt < 4; mt++)
                LDSM4(a[mt][0], a[mt][1], a[mt][2], a[mt][3],
                      abase + mt * (16 * RSH * 2) + ks * 32);
#pragma unroll
            for (int nt2 = 0; nt2 < 2; nt2++)
                LDSM4(b[nt2][0], b[nt2][1], b[nt2][2], b[nt2][3],
                      bbase + nt2 * (16 * RSH * 2) + ks * 32);
#pragma unroll
            for (int mt = 0; mt < 4; mt++) {
                mma_bf16(acc[mt][0], a[mt], b[0][0], b[0][1]);
                mma_bf16(acc[mt][1], a[mt], b[0][2], b[0][3]);
                mma_bf16(acc[mt][2], a[mt], b[1][0], b[1][1]);
                mma_bf16(acc[mt][3], a[mt], b[1][2], b[1][3]);
            }
        }
    }
    asm volatile("cp.async.wait_group 0;" ::: "memory");
    __syncthreads();

    if (MODE == 0) {
        __nv_bfloat16* C = (__nv_bfloat16*)Cv;
        const int which = (n0 >> 7) & 3;   // 0=q,1=k1,2=k2,3=v
        float inv[4][2];
#pragma unroll
        for (int mt = 0; mt < 4; mt++) { inv[mt][0] = 1.f; inv[mt][1] = 1.f; }
        if (which < 3) {
#pragma unroll
            for (int mt = 0; mt < 4; mt++)
#pragma unroll
                for (int nt = 0; nt < 4; nt++)
#pragma unroll
                    for (int c = 0; c < 4; c++) {
                        float x = acc[mt][nt][c];
                        acc[mt][nt][c] = (x > 0.f) ? x + 1.f : __expf(x);
                    }
#pragma unroll
            for (int mt = 0; mt < 4; mt++)
#pragma unroll
                for (int hh = 0; hh < 2; hh++) {
                    float v = 0.f;
#pragma unroll
                    for (int nt = 0; nt < 4; nt++)
                        v += acc[mt][nt][hh * 2] + acc[mt][nt][hh * 2 + 1];
                    v += __shfl_xor_sync(0xffffffffu, v, 1);
                    v += __shfl_xor_sync(0xffffffffu, v, 2);
                    if (qc == 0)
                        smf[(wR * 64 + mt * 16 + hh * 8 + qr) * 4 + wC] = v;
                }
            __syncthreads();
#pragma unroll
            for (int mt = 0; mt < 4; mt++)
#pragma unroll
                for (int hh = 0; hh < 2; hh++) {
                    int row = wR * 64 + mt * 16 + hh * 8 + qr;
                    float s = smf[row * 4 + 0] + smf[row * 4 + 1] +
                              smf[row * 4 + 2] + smf[row * 4 + 3];
                    inv[mt][hh] = 1.f / s;
                }
        }
#pragma unroll
        for (int mt = 0; mt < 4; mt++)
#pragma unroll
            for (int hh = 0; hh < 2; hh++) {
                const int row = m0 + wR * 64 + mt * 16 + hh * 8 + qr;
                const float iv = inv[mt][hh];
#pragma unroll
                for (int nt = 0; nt < 4; nt++) {
                    uint32_t o = pack_bf16x2(acc[mt][nt][hh * 2] * iv,
                                             acc[mt][nt][hh * 2 + 1] * iv);
                    *(uint32_t*)(C + (size_t)row * NC + n0 + wC * 32 + nt * 8 + qc * 2) = o;
                }
            }
    } else {
        float* C = (float*)Cv;
#pragma unroll
        for (int mt = 0; mt < 4; mt++)
#pragma unroll
            for (int hh = 0; hh < 2; hh++) {
                const int row = m0 + wR * 64 + mt * 16 + hh * 8 + qr;
#pragma unroll
                for (int nt = 0; nt < 4; nt++) {
                    const int col = n0 + wC * 32 + nt * 8 + qc * 2;
                    float2 rr = *(const float2*)(R + (size_t)row * DM + col);
                    float2 o;
                    o.x = acc[mt][nt][hh * 2]     + rr.x;
                    o.y = acc[mt][nt][hh * 2 + 1] + rr.y;
                    *(float2*)(C + (size_t)row * NC + col) = o;
                }
            }
    }
}

// ======================= tensor-core dual causal linear attention (R7, validated) =======================
#define ARS 136                      // qkv tile row stride (halves)
#define PRS 72                       // P tile row stride (halves)
#define ATTN_SMEM_HALVES (4 * 64 * ARS + 64 * PRS)
#define ATTN_SMEM_BYTES (ATTN_SMEM_HALVES * 2)   // 78848

__global__ void __launch_bounds__(256, 2)
attn_mma(const float* __restrict__ pi0)
{
    extern __shared__ __align__(16) __nv_bfloat16 smh[];
    __nv_bfloat16* Qs  = smh;
    __nv_bfloat16* K1s = Qs  + 64 * ARS;
    __nv_bfloat16* K2s = K1s + 64 * ARS;
    __nv_bfloat16* Vs  = K2s + 64 * ARS;
    __nv_bfloat16* Ps  = Vs  + 64 * ARS;
    uint32_t* Pu = (uint32_t*)Ps;

    const int tid = threadIdx.x;
    const int wid = tid >> 5, lane = tid & 31;
    const int wm = wid >> 1, wn = wid & 1;
    const int qr = lane >> 2, qc = lane & 3;
    const int tt = blockIdx.x;
    const int bh = blockIdx.y;
    const int b  = bh >> 3, head = bh & 7;
    const int t0 = tt * 64;

    const int lrow = tid >> 2, lch = (tid & 3) * 4;

    // load Q tile (full 64 x 128 halves)
#pragma unroll
    for (int c = 0; c < 4; c++) {
        int ch = lch + c;
        cp16(&Qs[lrow * ARS + ch * 8],
             g_qkvb + ((size_t)(t0 + lrow) * BSZ + b) * NQ + head * 512 + ch * 8);
    }
    asm volatile("cp.async.commit_group;" ::: "memory");

    const float pa = fminf(fmaxf(pi0[head * 256 + t0 + wm * 16 + qr], 0.f), 1.f);
    const float pb = fminf(fmaxf(pi0[head * 256 + t0 + wm * 16 + qr + 8], 0.f), 1.f);

    float o[8][4];
#pragma unroll
    for (int i = 0; i < 8; i++)
#pragma unroll
        for (int c = 0; c < 4; c++) o[i][c] = 0.f;

    const uint32_t qa_off = ((wm * 16 + (lane & 15)) * ARS + ((lane >> 4) << 3)) * 2;
    const uint32_t kb_off = ((wn * 32 + ((lane >> 4) << 3) + (lane & 7)) * ARS +
                             (((lane >> 3) & 1) << 3)) * 2;
    const uint32_t pa_off = ((wm * 16 + (lane & 15)) * PRS + ((lane >> 4) << 3)) * 2;
    const uint32_t vt_off = ((lane & 15) * ARS + wn * 64 + ((lane >> 4) << 3)) * 2;
    const uint32_t qbase = smem_u32(Qs), k1base = smem_u32(K1s), k2base = smem_u32(K2s);
    const uint32_t pbase = smem_u32(Ps), vbase = smem_u32(Vs);

#pragma unroll 1
    for (int st = 0; st <= tt; st++) {
        const int s0 = st * 64;
        if (st > 0) __syncthreads();
        {
            size_t gb = ((size_t)(s0 + lrow) * BSZ + b) * NQ + head * 512;
#pragma unroll
            for (int c = 0; c < 4; c++) {
                int ch = lch + c;
                cp16(&K1s[lrow * ARS + ch * 8], g_qkvb + gb + 128 + ch * 8);
                cp16(&K2s[lrow * ARS + ch * 8], g_qkvb + gb + 256 + ch * 8);
                cp16(&Vs [lrow * ARS + ch * 8], g_qkvb + gb + 384 + ch * 8);
            }
        }
        asm volatile("cp.async.commit_group;" ::: "memory");
        asm volatile("cp.async.wait_group 0;" ::: "memory");
        __syncthreads();

        // ---- S phase ----
        float s1[4][4], s2[4][4];
#pragma unroll
        for (int nc = 0; nc < 4; nc++)
#pragma unroll
            for (int c = 0; c < 4; c++) { s1[nc][c] = 0.f; s2[nc][c] = 0.f; }

#pragma unroll
        for (int ks = 0; ks < 8; ks++) {
            uint32_t a[4], b1[2][4], b2[2][4];
            LDSM4(a[0], a[1], a[2], a[3], qbase + qa_off + ks * 32);
#pragma unroll
            for (int g = 0; g < 2; g++) {
                LDSM4(b1[g][0], b1[g][1], b1[g][2], b1[g][3],
                      k1base + kb_off + g * (16 * ARS * 2) + ks * 32);
                LDSM4(b2[g][0], b2[g][1], b2[g][2], b2[g][3],
                      k2base + kb_off + g * (16 * ARS * 2) + ks * 32);
            }
            mma_bf16(s1[0], a, b1[0][0], b1[0][1]);
            mma_bf16(s1[1], a, b1[0][2], b1[0][3]);
            mma_bf16(s1[2], a, b1[1][0], b1[1][1]);
            mma_bf16(s1[3], a, b1[1][2], b1[1][3]);
            mma_bf16(s2[0], a, b2[0][0], b2[0][1]);
            mma_bf16(s2[1], a, b2[0][2], b2[0][3]);
            mma_bf16(s2[2], a, b2[1][0], b2[1][1]);
            mma_bf16(s2[3], a, b2[1][2], b2[1][3]);
        }

        // ---- combine + mask -> P (bf16) ----
        const bool diag = (st == tt);
        const int tg0 = wm * 16 + qr, tg1 = tg0 + 8;
#pragma unroll
        for (int nc = 0; nc < 4; nc++) {
            const int c0 = wn * 32 + nc * 8 + qc * 2, c1 = c0 + 1;
            float v00 = s2[nc][0] + pa * (s1[nc][0] - s2[nc][0]);
            float v01 = s2[nc][1] + pa * (s1[nc][1] - s2[nc][1]);
            float v10 = s2[nc][2] + pb * (s1[nc][2] - s2[nc][2]);
            float v11 = s2[nc][3] + pb * (s1[nc][3] - s2[nc][3]);
            if (diag) {
                if (c0 > tg0) v00 = 0.f;
                if (c1 > tg0) v01 = 0.f;
                if (c0 > tg1) v10 = 0.f;
                if (c1 > tg1) v11 = 0.f;
            }
            Pu[tg0 * (PRS / 2) + (c0 >> 1)] = pack_bf16x2(v00, v01);
            Pu[tg1 * (PRS / 2) + (c0 >> 1)] = pack_bf16x2(v10, v11);
        }
        __syncthreads();

        // ---- PV phase ----
#pragma unroll
        for (int ks = 0; ks < 4; ks++) {
            uint32_t a[4];
            LDSM4(a[0], a[1], a[2], a[3], pbase + pa_off + ks * 32);
#pragma unroll
            for (int nc2 = 0; nc2 < 4; nc2++) {
                uint32_t b[4];
                LDSM4T(b[0], b[1], b[2], b[3],
                       vbase + vt_off + ks * (16 * ARS * 2) + nc2 * 32);
                mma_bf16(o[nc2 * 2],     a, b[0], b[1]);
                mma_bf16(o[nc2 * 2 + 1], a, b[2], b[3]);
            }
        }
    }

    // ---- store O * SCALE -> g_lob bf16 ----
#pragma unroll
    for (int i = 0; i < 8; i++) {
        const int dh = head * DH + wn * 64 + i * 8 + qc * 2;
        const int ta = t0 + wm * 16 + qr, tb2 = ta + 8;
        *(uint32_t*)(g_lob + ((size_t)ta * BSZ + b) * DM + dh) =
            pack_bf16x2(SCALE_F * o[i][0], SCALE_F * o[i][1]);
        *(uint32_t*)(g_lob + ((size_t)tb2 * BSZ + b) * DM + dh) =
            pack_bf16x2(SCALE_F * o[i][2], SCALE_F * o[i][3]);
    }
}

// ======================= LayerNorm =======================
__global__ void __launch_bounds__(256)
ln_kernel(const float* __restrict__ gamma, const float* __restrict__ beta,
          float* __restrict__ out)
{
    __shared__ float red[8];
    const int r = blockIdx.x, tid = threadIdx.x;
    const int lane = tid & 31, wid = tid >> 5;
    float4 v = *(const float4*)&g_x[(size_t)r * DM + tid * 4];
    float s = v.x + v.y + v.z + v.w;
#pragma unroll
    for (int o = 16; o > 0; o >>= 1) s += __shfl_xor_sync(0xffffffffu, s, o);
    if (lane == 0) red[wid] = s;
    __syncthreads();
    float tot = 0.f;
#pragma unroll
    for (int i = 0; i < 8; i++) tot += red[i];
    float mu = tot * (1.f / DM);
    float d0 = v.x - mu, d1 = v.y - mu, d2 = v.z - mu, d3 = v.w - mu;
    float sq = d0*d0 + d1*d1 + d2*d2 + d3*d3;
#pragma unroll
    for (int o = 16; o > 0; o >>= 1) sq += __shfl_xor_sync(0xffffffffu, sq, o);
    __syncthreads();
    if (lane == 0) red[wid] = sq;
    __syncthreads();
    float tot2 = 0.f;
#pragma unroll
    for (int i = 0; i < 8; i++) tot2 += red[i];
    float inv = rsqrtf(tot2 * (1.f / DM) + LN_EPS_F);
    float4 g = *(const float4*)&gamma[tid * 4];
    float4 bt = *(const float4*)&beta[tid * 4];
    float4 o;
    o.x = g.x * d0 * inv + bt.x;
    o.y = g.y * d1 * inv + bt.y;
    o.z = g.z * d2 * inv + bt.z;
    o.w = g.w * d3 * inv + bt.w;
    *(float4*)&out[(size_t)r * DM + tid * 4] = o;
}

// ======================= launch =======================
extern "C" void kernel_launch(void* const* d_in, const int* in_sizes, int n_in,
                              void* d_out, int out_size)
{
    const float* h     = (const float*)d_in[0];
    const float* Wqkv  = (const float*)d_in[1];
    const float* Wo    = (const float*)d_in[2];
    const float* pi0   = (const float*)d_in[3];
    const float* gamma = (const float*)d_in[4];
    const float* beta  = (const float*)d_in[5];
    float* out = (float*)d_out;

    float *p_x;
    __nv_bfloat16 *p_hb, *p_wqb, *p_wob, *p_lob, *p_qkvb;
    cudaGetSymbolAddress((void**)&p_x, g_x);
    cudaGetSymbolAddress((void**)&p_hb, g_hb);
    cudaGetSymbolAddress((void**)&p_wqb, g_wqb);
    cudaGetSymbolAddress((void**)&p_wob, g_wob);
    cudaGetSymbolAddress((void**)&p_lob, g_lob);
    cudaGetSymbolAddress((void**)&p_qkvb, g_qkvb);

    cudaFuncSetAttribute(gemm_mma<0>, cudaFuncAttributeMaxDynamicSharedMemorySize, GEMM_SMEM_BYTES);
    cudaFuncSetAttribute(gemm_mma<1>, cudaFuncAttributeMaxDynamicSharedMemorySize, GEMM_SMEM_BYTES);
    cudaFuncSetAttribute(attn_mma, cudaFuncAttributeMaxDynamicSharedMemorySize, ATTN_SMEM_BYTES);

    // 0. convert inputs to bf16
    cvt_bf16<<<(MROWS * DM) / 1024, 256>>>(h, p_hb);
    cvt_bf16<<<(NQ * DM) / 1024, 256>>>(Wqkv, p_wqb);
    cvt_bf16<<<(DM * DM) / 1024, 256>>>(Wo, p_wob);

    // 1. qkv = h @ Wqkv^T (bf16 mma), phi fused, bf16 out
    gemm_mma<0><<<dim3(NQ / 128, MROWS / 128), 256, GEMM_SMEM_BYTES>>>(p_hb, p_wqb, nullptr, p_qkvb, NQ);

    // 2. tensor-core dual causal linear attention -> g_lob (bf16)
    attn_mma<<<dim3(LSEQ / 64, BSZ * NH), 256, ATTN_SMEM_BYTES>>>(pi0);

    // 3. x = layer_out @ Wo^T + h (residual fused)
    gemm_mma<1><<<dim3(DM / 128, MROWS / 128), 256, GEMM_SMEM_BYTES>>>(p_lob, p_wob, h, p_x, DM);

    // 4. LayerNorm -> out
    ln_kernel<<<MROWS, 256>>>(gamma, beta, out);
}

// round 14
// speedup vs baseline: 1.9689x; 1.2783x over previous
#include <cuda_runtime.h>
#include <cuda_bf16.h>
#include <cstdint>
#include <math.h>

#define LSEQ 256
#define BSZ  64
#define NH   8
#define DH   128
#define DM   1024
#define NQ   4096
#define MROWS (LSEQ*BSZ)
#define SCALE_F 0.08838834764831845f
#define LN_EPS_F 1e-5f

// ---- scratch (static device arrays; no allocation) ----
__device__ __align__(256) float g_x  [(size_t)MROWS * DM];           // h + attn_out fp32
__device__ __align__(256) __nv_bfloat16 g_qkvb[(size_t)MROWS * NQ];  // phi(q,k1,k2), v  bf16
__device__ __align__(256) __nv_bfloat16 g_hb [(size_t)MROWS * DM];   // h bf16
__device__ __align__(256) __nv_bfloat16 g_wqb[(size_t)NQ * DM];      // Wqkv bf16
__device__ __align__(256) __nv_bfloat16 g_wob[(size_t)DM * DM];      // Wo bf16
__device__ __align__(256) __nv_bfloat16 g_lob[(size_t)MROWS * DM];   // layer_out bf16

// ======================= helpers =======================
__device__ __forceinline__ uint32_t smem_u32(const void* p) {
    uint32_t a;
    asm("{ .reg .u64 t; cvta.to.shared.u64 t, %1; cvt.u32.u64 %0, t; }" : "=r"(a) : "l"(p));
    return a;
}
__device__ __forceinline__ void cp16(void* s, const void* g) {
    uint32_t sa = smem_u32(s);
    asm volatile("cp.async.cg.shared.global [%0], [%1], 16;" :: "r"(sa), "l"(g));
}
#define LDSM4(r0, r1, r2, r3, addr) \
    asm volatile("ldmatrix.sync.aligned.m8n8.x4.shared.b16 {%0,%1,%2,%3}, [%4];" \
                 : "=r"(r0), "=r"(r1), "=r"(r2), "=r"(r3) : "r"(addr))
#define LDSM4T(r0, r1, r2, r3, addr) \
    asm volatile("ldmatrix.sync.aligned.m8n8.x4.trans.shared.b16 {%0,%1,%2,%3}, [%4];" \
                 : "=r"(r0), "=r"(r1), "=r"(r2), "=r"(r3) : "r"(addr))
__device__ __forceinline__ void mma_bf16(float* d, const uint32_t* a,
                                         uint32_t b0, uint32_t b1) {
    asm volatile(
        "mma.sync.aligned.m16n8k16.row.col.f32.bf16.bf16.f32 "
        "{%0,%1,%2,%3}, {%4,%5,%6,%7}, {%8,%9}, {%0,%1,%2,%3};"
        : "+f"(d[0]), "+f"(d[1]), "+f"(d[2]), "+f"(d[3])
        : "r"(a[0]), "r"(a[1]), "r"(a[2]), "r"(a[3]), "r"(b0), "r"(b1));
}
__device__ __forceinline__ uint32_t pack_bf16x2(float x, float y) {
    __nv_bfloat162 p = __floats2bfloat162_rn(x, y);
    return *(uint32_t*)&p;
}

// ======================= fp32 -> bf16 conversion pass =======================
__global__ void __launch_bounds__(256)
cvt_bf16(const float* __restrict__ src, __nv_bfloat16* __restrict__ dst)
{
    size_t i = ((size_t)blockIdx.x * 256 + threadIdx.x) * 4;
    float4 v = *(const float4*)(src + i);
    uint2 o;
    o.x = pack_bf16x2(v.x, v.y);
    o.y = pack_bf16x2(v.z, v.w);
    *(uint2*)(dst + i) = o;
}

// ======================= bf16 mma.sync GEMM: C = A * B^T =======================
// CTA 128x128, 8 warps (2x4), warp 64x32, KB=64 halves/stage, 3-stage cp.async,
// ldmatrix.x4, 72-half padded row stride. Loader: warp = 4 rows x 8 contiguous
// 16B chunks (full 128B lines, fully coalesced).
// MODE 0: C = g_qkvb (bf16, NC=4096), epilogue = phi on q/k1/k2 groups
// MODE 1: C = g_x (fp32, NC=1024), epilogue = + residual R (h fp32)
#define KB 64
#define GITERS (DM / KB)            // 16
#define STG 3
#define RSH 72                      // row stride in halves (144 bytes)
#define STAGE_HALVES (128 * RSH)    // 9216 halves = 18432 B
#define GEMM_SMEM_BYTES (STG * 2 * STAGE_HALVES * 2)   // 110592

template<int MODE>
__global__ void __launch_bounds__(256, 2)
gemm_mma(const __nv_bfloat16* __restrict__ A, const __nv_bfloat16* __restrict__ Bm,
         const float* __restrict__ R, void* __restrict__ Cv, int NC)
{
    extern __shared__ __align__(16) char smraw[];
    __nv_bfloat16* smh = (__nv_bfloat16*)smraw;
    float* smf = (float*)smraw;
    const int tid = threadIdx.x;
    const int wid = tid >> 5, lane = tid & 31;
    const int wR = wid >> 2, wC = wid & 3;
    const int qr = lane >> 2, qc = lane & 3;
    const int m0 = blockIdx.y * 128, n0 = blockIdx.x * 128;

    float acc[4][4][4];
#pragma unroll
    for (int mt = 0; mt < 4; mt++)
#pragma unroll
        for (int nt = 0; nt < 4; nt++)
#pragma unroll
            for (int c = 0; c < 4; c++) acc[mt][nt][c] = 0.f;

    // coalesced loader mapping: 8 threads cover one row's 128B contiguously
    const int lrow8 = tid >> 3;           // 0..31 (row within 32-row pass)
    const int lch8  = (tid & 7) * 8;      // halves offset (0..56) -> 16B chunks

    auto issue = [&](int it) {
        if (it < GITERS) {
            const int s = it % STG;
            __nv_bfloat16* As = smh + s * 2 * STAGE_HALVES;
            __nv_bfloat16* Bs = As + STAGE_HALVES;
            const int k0 = it * KB;
#pragma unroll
            for (int p = 0; p < 4; p++) {
                const int row = lrow8 + p * 32;
                cp16(&As[row * RSH + lch8], A  + (size_t)(m0 + row) * DM + k0 + lch8);
                cp16(&Bs[row * RSH + lch8], Bm + (size_t)(n0 + row) * DM + k0 + lch8);
            }
        }
        asm volatile("cp.async.commit_group;" ::: "memory");
    };

    issue(0);
    issue(1);

    const uint32_t a_lane_off = ((wR * 64 + (lane & 15)) * RSH + ((lane >> 4) << 3)) * 2;
    const uint32_t b_lane_off = ((wC * 32 + ((lane >> 4) << 3) + (lane & 7)) * RSH +
                                 (((lane >> 3) & 1) << 3)) * 2;

#pragma unroll 1
    for (int it = 0; it < GITERS; ++it) {
        asm volatile("cp.async.wait_group 1;" ::: "memory");
        __syncthreads();
        issue(it + 2);

        const int s = it % STG;
        const uint32_t abase = smem_u32(smh + s * 2 * STAGE_HALVES) + a_lane_off;
        const uint32_t bbase = smem_u32(smh + s * 2 * STAGE_HALVES + STAGE_HALVES) + b_lane_off;

#pragma unroll
        for (int ks = 0; ks < 4; ks++) {    // 4 x k16 (32 bytes each within 64-half stage)
            uint32_t a[4][4], b[2][4];
#pragma unroll
            for (int mt = 0; mt < 4; mt++)
                LDSM4(a[mt][0], a[mt][1], a[mt][2], a[mt][3],
                      abase + mt * (16 * RSH * 2) + ks * 32);
#pragma unroll
            for (int nt2 = 0; nt2 < 2; nt2++)
                LDSM4(b[nt2][0], b[nt2][1], b[nt2][2], b[nt2][3],
                      bbase + nt2 * (16 * RSH * 2) + ks * 32);
#pragma unroll
            for (int mt = 0; mt < 4; mt++) {
                mma_bf16(acc[mt][0], a[mt], b[0][0], b[0][1]);
                mma_bf16(acc[mt][1], a[mt], b[0][2], b[0][3]);
                mma_bf16(acc[mt][2], a[mt], b[1][0], b[1][1]);
                mma_bf16(acc[mt][3], a[mt], b[1][2], b[1][3]);
            }
        }
    }
    asm volatile("cp.async.wait_group 0;" ::: "memory");
    __syncthreads();

    if (MODE == 0) {
        __nv_bfloat16* C = (__nv_bfloat16*)Cv;
        const int which = (n0 >> 7) & 3;   // 0=q,1=k1,2=k2,3=v
        float inv[4][2];
#pragma unroll
        for (int mt = 0; mt < 4; mt++) { inv[mt][0] = 1.f; inv[mt][1] = 1.f; }
        if (which < 3) {
#pragma unroll
            for (int mt = 0; mt < 4; mt++)
#pragma unroll
                for (int nt = 0; nt < 4; nt++)
#pragma unroll
                    for (int c = 0; c < 4; c++) {
                        float x = acc[mt][nt][c];
                        acc[mt][nt][c] = (x > 0.f) ? x + 1.f : __expf(x);
                    }
#pragma unroll
            for (int mt = 0; mt < 4; mt++)
#pragma unroll
                for (int hh = 0; hh < 2; hh++) {
                    float v = 0.f;
#pragma unroll
                    for (int nt = 0; nt < 4; nt++)
                        v += acc[mt][nt][hh * 2] + acc[mt][nt][hh * 2 + 1];
                    v += __shfl_xor_sync(0xffffffffu, v, 1);
                    v += __shfl_xor_sync(0xffffffffu, v, 2);
                    if (qc == 0)
                        smf[(wR * 64 + mt * 16 + hh * 8 + qr) * 4 + wC] = v;
                }
            __syncthreads();
#pragma unroll
            for (int mt = 0; mt < 4; mt++)
#pragma unroll
                for (int hh = 0; hh < 2; hh++) {
                    int row = wR * 64 + mt * 16 + hh * 8 + qr;
                    float s = smf[row * 4 + 0] + smf[row * 4 + 1] +
                              smf[row * 4 + 2] + smf[row * 4 + 3];
                    inv[mt][hh] = 1.f / s;
                }
        }
#pragma unroll
        for (int mt = 0; mt < 4; mt++)
#pragma unroll
            for (int hh = 0; hh < 2; hh++) {
                const int row = m0 + wR * 64 + mt * 16 + hh * 8 + qr;
                const float iv = inv[mt][hh];
#pragma unroll
                for (int nt = 0; nt < 4; nt++) {
                    uint32_t o = pack_bf16x2(acc[mt][nt][hh * 2] * iv,
                                             acc[mt][nt][hh * 2 + 1] * iv);
                    *(uint32_t*)(C + (size_t)row * NC + n0 + wC * 32 + nt * 8 + qc * 2) = o;
                }
            }
    } else {
        float* C = (float*)Cv;
#pragma unroll
        for (int mt = 0; mt < 4; mt++)
#pragma unroll
            for (int hh = 0; hh < 2; hh++) {
                const int row = m0 + wR * 64 + mt * 16 + hh * 8 + qr;
#pragma unroll
                for (int nt = 0; nt < 4; nt++) {
                    const int col = n0 + wC * 32 + nt * 8 + qc * 2;
                    float2 rr = *(const float2*)(R + (size_t)row * DM + col);
                    float2 o;
                    o.x = acc[mt][nt][hh * 2]     + rr.x;
                    o.y = acc[mt][nt][hh * 2 + 1] + rr.y;
                    *(float2*)(C + (size_t)row * NC + col) = o;
                }
            }
    }
}

// ======================= tensor-core dual causal linear attention (R7, validated) =======================
#define ARS 136                      // qkv tile row stride (halves)
#define PRS 72                       // P tile row stride (halves)
#define ATTN_SMEM_HALVES (4 * 64 * ARS + 64 * PRS)
#define ATTN_SMEM_BYTES (ATTN_SMEM_HALVES * 2)   // 78848

__global__ void __launch_bounds__(256, 2)
attn_mma(const float* __restrict__ pi0)
{
    extern __shared__ __align__(16) __nv_bfloat16 smh[];
    __nv_bfloat16* Qs  = smh;
    __nv_bfloat16* K1s = Qs  + 64 * ARS;
    __nv_bfloat16* K2s = K1s + 64 * ARS;
    __nv_bfloat16* Vs  = K2s + 64 * ARS;
    __nv_bfloat16* Ps  = Vs  + 64 * ARS;
    uint32_t* Pu = (uint32_t*)Ps;

    const int tid = threadIdx.x;
    const int wid = tid >> 5, lane = tid & 31;
    const int wm = wid >> 1, wn = wid & 1;
    const int qr = lane >> 2, qc = lane & 3;
    const int tt = blockIdx.x;
    const int bh = blockIdx.y;
    const int b  = bh >> 3, head = bh & 7;
    const int t0 = tt * 64;

    const int lrow = tid >> 2, lch = (tid & 3) * 4;

    // load Q tile (full 64 x 128 halves)
#pragma unroll
    for (int c = 0; c < 4; c++) {
        int ch = lch + c;
        cp16(&Qs[lrow * ARS + ch * 8],
             g_qkvb + ((size_t)(t0 + lrow) * BSZ + b) * NQ + head * 512 + ch * 8);
    }
    asm volatile("cp.async.commit_group;" ::: "memory");

    const float pa = fminf(fmaxf(pi0[head * 256 + t0 + wm * 16 + qr], 0.f), 1.f);
    const float pb = fminf(fmaxf(pi0[head * 256 + t0 + wm * 16 + qr + 8], 0.f), 1.f);

    float o[8][4];
#pragma unroll
    for (int i = 0; i < 8; i++)
#pragma unroll
        for (int c = 0; c < 4; c++) o[i][c] = 0.f;

    const uint32_t qa_off = ((wm * 16 + (lane & 15)) * ARS + ((lane >> 4) << 3)) * 2;
    const uint32_t kb_off = ((wn * 32 + ((lane >> 4) << 3) + (lane & 7)) * ARS +
                             (((lane >> 3) & 1) << 3)) * 2;
    const uint32_t pa_off = ((wm * 16 + (lane & 15)) * PRS + ((lane >> 4) << 3)) * 2;
    const uint32_t vt_off = ((lane & 15) * ARS + wn * 64 + ((lane >> 4) << 3)) * 2;
    const uint32_t qbase = smem_u32(Qs), k1base = smem_u32(K1s), k2base = smem_u32(K2s);
    const uint32_t pbase = smem_u32(Ps), vbase = smem_u32(Vs);

#pragma unroll 1
    for (int st = 0; st <= tt; st++) {
        const int s0 = st * 64;
        if (st > 0) __syncthreads();
        {
            size_t gb = ((size_t)(s0 + lrow) * BSZ + b) * NQ + head * 512;
#pragma unroll
            for (int c = 0; c < 4; c++) {
                int ch = lch + c;
                cp16(&K1s[lrow * ARS + ch * 8], g_qkvb + gb + 128 + ch * 8);
                cp16(&K2s[lrow * ARS + ch * 8], g_qkvb + gb + 256 + ch * 8);
                cp16(&Vs [lrow * ARS + ch * 8], g_qkvb + gb + 384 + ch * 8);
            }
        }
        asm volatile("cp.async.commit_group;" ::: "memory");
        asm volatile("cp.async.wait_group 0;" ::: "memory");
        __syncthreads();

        // ---- S phase ----
        float s1[4][4], s2[4][4];
#pragma unroll
        for (int nc = 0; nc < 4; nc++)
#pragma unroll
            for (int c = 0; c < 4; c++) { s1[nc][c] = 0.f; s2[nc][c] = 0.f; }

#pragma unroll
        for (int ks = 0; ks < 8; ks++) {
            uint32_t a[4], b1[2][4], b2[2][4];
            LDSM4(a[0], a[1], a[2], a[3], qbase + qa_off + ks * 32);
#pragma unroll
            for (int g = 0; g < 2; g++) {
                LDSM4(b1[g][0], b1[g][1], b1[g][2], b1[g][3],
                      k1base + kb_off + g * (16 * ARS * 2) + ks * 32);
                LDSM4(b2[g][0], b2[g][1], b2[g][2], b2[g][3],
                      k2base + kb_off + g * (16 * ARS * 2) + ks * 32);
            }
            mma_bf16(s1[0], a, b1[0][0], b1[0][1]);
            mma_bf16(s1[1], a, b1[0][2], b1[0][3]);
            mma_bf16(s1[2], a, b1[1][0], b1[1][1]);
            mma_bf16(s1[3], a, b1[1][2], b1[1][3]);
            mma_bf16(s2[0], a, b2[0][0], b2[0][1]);
            mma_bf16(s2[1], a, b2[0][2], b2[0][3]);
            mma_bf16(s2[2], a, b2[1][0], b2[1][1]);
            mma_bf16(s2[3], a, b2[1][2], b2[1][3]);
        }

        // ---- combine + mask -> P (bf16) ----
        const bool diag = (st == tt);
        const int tg0 = wm * 16 + qr, tg1 = tg0 + 8;
#pragma unroll
        for (int nc = 0; nc < 4; nc++) {
            const int c0 = wn * 32 + nc * 8 + qc * 2, c1 = c0 + 1;
            float v00 = s2[nc][0] + pa * (s1[nc][0] - s2[nc][0]);
            float v01 = s2[nc][1] + pa * (s1[nc][1] - s2[nc][1]);
            float v10 = s2[nc][2] + pb * (s1[nc][2] - s2[nc][2]);
            float v11 = s2[nc][3] + pb * (s1[nc][3] - s2[nc][3]);
            if (diag) {
                if (c0 > tg0) v00 = 0.f;
                if (c1 > tg0) v01 = 0.f;
                if (c0 > tg1) v10 = 0.f;
                if (c1 > tg1) v11 = 0.f;
            }
            Pu[tg0 * (PRS / 2) + (c0 >> 1)] = pack_bf16x2(v00, v01);
            Pu[tg1 * (PRS / 2) + (c0 >> 1)] = pack_bf16x2(v10, v11);
        }
        __syncthreads();

        // ---- PV phase ----
#pragma unroll
        for (int ks = 0; ks < 4; ks++) {
            uint32_t a[4];
            LDSM4(a[0], a[1], a[2], a[3], pbase + pa_off + ks * 32);
#pragma unroll
            for (int nc2 = 0; nc2 < 4; nc2++) {
                uint32_t b[4];
                LDSM4T(b[0], b[1], b[2], b[3],
                       vbase + vt_off + ks * (16 * ARS * 2) + nc2 * 32);
                mma_bf16(o[nc2 * 2],     a, b[0], b[1]);
                mma_bf16(o[nc2 * 2 + 1], a, b[2], b[3]);
            }
        }
    }

    // ---- store O * SCALE -> g_lob bf16 ----
#pragma unroll
    for (int i = 0; i < 8; i++) {
        const int dh = head * DH + wn * 64 + i * 8 + qc * 2;
        const int ta = t0 + wm * 16 + qr, tb2 = ta + 8;
        *(uint32_t*)(g_lob + ((size_t)ta * BSZ + b) * DM + dh) =
            pack_bf16x2(SCALE_F * o[i][0], SCALE_F * o[i][1]);
        *(uint32_t*)(g_lob + ((size_t)tb2 * BSZ + b) * DM + dh) =
            pack_bf16x2(SCALE_F * o[i][2], SCALE_F * o[i][3]);
    }
}

// ======================= LayerNorm =======================
__global__ void __launch_bounds__(256)
ln_kernel(const float* __restrict__ gamma, const float* __restrict__ beta,
          float* __restrict__ out)
{
    __shared__ float red[8];
    const int r = blockIdx.x, tid = threadIdx.x;
    const int lane = tid & 31, wid = tid >> 5;
    float4 v = *(const float4*)&g_x[(size_t)r * DM + tid * 4];
    float s = v.x + v.y + v.z + v.w;
#pragma unroll
    for (int o = 16; o > 0; o >>= 1) s += __shfl_xor_sync(0xffffffffu, s, o);
    if (lane == 0) red[wid] = s;
    __syncthreads();
    float tot = 0.f;
#pragma unroll
    for (int i = 0; i < 8; i++) tot += red[i];
    float mu = tot * (1.f / DM);
    float d0 = v.x - mu, d1 = v.y - mu, d2 = v.z - mu, d3 = v.w - mu;
    float sq = d0*d0 + d1*d1 + d2*d2 + d3*d3;
#pragma unroll
    for (int o = 16; o > 0; o >>= 1) sq += __shfl_xor_sync(0xffffffffu, sq, o);
    __syncthreads();
    if (lane == 0) red[wid] = sq;
    __syncthreads();
    float tot2 = 0.f;
#pragma unroll
    for (int i = 0; i < 8; i++) tot2 += red[i];
    float inv = rsqrtf(tot2 * (1.f / DM) + LN_EPS_F);
    float4 g = *(const float4*)&gamma[tid * 4];
    float4 bt = *(const float4*)&beta[tid * 4];
    float4 o;
    o.x = g.x * d0 * inv + bt.x;
    o.y = g.y * d1 * inv + bt.y;
    o.z = g.z * d2 * inv + bt.z;
    o.w = g.w * d3 * inv + bt.w;
    *(float4*)&out[(size_t)r * DM + tid * 4] = o;
}

// ======================= launch =======================
extern "C" void kernel_launch(void* const* d_in, const int* in_sizes, int n_in,
                              void* d_out, int out_size)
{
    const float* h     = (const float*)d_in[0];
    const float* Wqkv  = (const float*)d_in[1];
    const float* Wo    = (const float*)d_in[2];
    const float* pi0   = (const float*)d_in[3];
    const float* gamma = (const float*)d_in[4];
    const float* beta  = (const float*)d_in[5];
    float* out = (float*)d_out;

    float *p_x;
    __nv_bfloat16 *p_hb, *p_wqb, *p_wob, *p_lob, *p_qkvb;
    cudaGetSymbolAddress((void**)&p_x, g_x);
    cudaGetSymbolAddress((void**)&p_hb, g_hb);
    cudaGetSymbolAddress((void**)&p_wqb, g_wqb);
    cudaGetSymbolAddress((void**)&p_wob, g_wob);
    cudaGetSymbolAddress((void**)&p_lob, g_lob);
    cudaGetSymbolAddress((void**)&p_qkvb, g_qkvb);

    cudaFuncSetAttribute(gemm_mma<0>, cudaFuncAttributeMaxDynamicSharedMemorySize, GEMM_SMEM_BYTES);
    cudaFuncSetAttribute(gemm_mma<1>, cudaFuncAttributeMaxDynamicSharedMemorySize, GEMM_SMEM_BYTES);
    cudaFuncSetAttribute(attn_mma, cudaFuncAttributeMaxDynamicSharedMemorySize, ATTN_SMEM_BYTES);

    // 0. convert inputs to bf16
    cvt_bf16<<<(MROWS * DM) / 1024, 256>>>(h, p_hb);
    cvt_bf16<<<(NQ * DM) / 1024, 256>>>(Wqkv, p_wqb);
    cvt_bf16<<<(DM * DM) / 1024, 256>>>(Wo, p_wob);

    // 1. qkv = h @ Wqkv^T (bf16 mma), phi fused, bf16 out
    gemm_mma<0><<<dim3(NQ / 128, MROWS / 128), 256, GEMM_SMEM_BYTES>>>(p_hb, p_wqb, nullptr, p_qkvb, NQ);

    // 2. tensor-core dual causal linear attention -> g_lob (bf16)
    attn_mma<<<dim3(LSEQ / 64, BSZ * NH), 256, ATTN_SMEM_BYTES>>>(pi0);

    // 3. x = layer_out @ Wo^T + h (residual fused)
    gemm_mma<1><<<dim3(DM / 128, MROWS / 128), 256, GEMM_SMEM_BYTES>>>(p_lob, p_wob, h, p_x, DM);

    // 4. LayerNorm -> out
    ln_kernel<<<MROWS, 256>>>(gamma, beta, out);
}